// round 4
// baseline (speedup 1.0000x reference)
#include <cuda_runtime.h>
#include <cstdint>

// Problem constants
#define DD   256
#define NQ   4
#define KK   1024
#define NTOT 131072

#define ROWS     128
#define NTHREADS 256
#define MARGIN   0.2f

// Scratch
__device__ float    g_res[(size_t)NTOT * DD];            // residual, row-major
__device__ uint32_t g_afrag[(size_t)(NTOT/ROWS) * 8 * 4096]; // A tf32 frags [b][dc][1024 pos][4]
__device__ uint32_t g_bfrag[(size_t)NQ * 8 * 8 * 4096];      // B tf32 frags [s][cc][dc][tile]
__device__ float    g_c2[NQ * KK];

// ---------------- helpers ----------------
__device__ __forceinline__ uint32_t to_tf32(float f) {
    uint32_t r; asm("cvt.rna.tf32.f32 %0, %1;" : "=r"(r) : "f"(f)); return r;
}
__device__ __forceinline__ void cpasync16(uint32_t s, const void* g) {
    asm volatile("cp.async.cg.shared.global [%0], [%1], 16;" :: "r"(s), "l"(g));
}

#define MMA_TF32(d, a, bb) \
    asm volatile("mma.sync.aligned.m16n8k8.row.col.f32.tf32.tf32.f32 " \
        "{%0,%1,%2,%3},{%4,%5,%6,%7},{%8,%9},{%0,%1,%2,%3};" \
        : "+f"((d)[0]), "+f"((d)[1]), "+f"((d)[2]), "+f"((d)[3]) \
        : "r"((a).x), "r"((a).y), "r"((a).z), "r"((a).w), "r"((bb).x), "r"((bb).y))

// ---------------- prep kernels ----------------
// B fragments: i bits = [s(2)][cc(3)][dc(3)][nt(4)][ks(2)][lane(5)]
__global__ void prep_b_k(const float* __restrict__ cb) {
    int i = blockIdx.x * blockDim.x + threadIdx.x;
    if (i >= NQ * 8 * 8 * 16 * 4 * 32) return;
    int lane = i & 31, ks = (i >> 5) & 3, nt = (i >> 7) & 15;
    int dc = (i >> 11) & 7, cc = (i >> 14) & 7, s = i >> 17;
    int n = cc * 128 + nt * 8 + (lane >> 2);
    int k = dc * 32 + ks * 8 + (lane & 3);
    const float* row = cb + ((size_t)s * KK + n) * DD;
    uint2 v;
    v.x = to_tf32(row[k]);
    v.y = to_tf32(row[k + 4]);
    ((uint2*)g_bfrag)[i] = v;
}

// A fragments from x (stage 0). One thread per uint4 position.
__global__ void prep_a0_k(const float* __restrict__ x) {
    int gp = blockIdx.x * blockDim.x + threadIdx.x;   // < 1024*8*1024
    int b = gp >> 13, dc = (gp >> 10) & 7, p = gp & 1023;
    int pl = p & 31, ks = (p >> 5) & 3, mt = (p >> 7) & 1, mg = (p >> 8) & 3;
    int r0 = mg * 32 + mt * 16 + (pl >> 2);
    int c0 = dc * 32 + ks * 8 + (pl & 3);
    const float* xb = x + ((size_t)b * ROWS) * DD;
    uint4 v;
    v.x = to_tf32(xb[(size_t)r0 * DD + c0]);
    v.y = to_tf32(xb[(size_t)(r0 + 8) * DD + c0]);
    v.z = to_tf32(xb[(size_t)r0 * DD + c0 + 4]);
    v.w = to_tf32(xb[(size_t)(r0 + 8) * DD + c0 + 4]);
    *(uint4*)&g_afrag[((size_t)b * 8 + dc) * 4096 + (size_t)p * 4] = v;
}

__global__ void copy_res_k(const float* __restrict__ x) {
    size_t i = (size_t)blockIdx.x * blockDim.x + threadIdx.x;
    ((float4*)g_res)[i] = ((const float4*)x)[i];
}
__global__ void c2_k(const float* __restrict__ cb) {
    int w = (blockIdx.x * blockDim.x + threadIdx.x) >> 5;
    int lane = threadIdx.x & 31;
    if (w >= NQ * KK) return;
    const float* row = cb + (size_t)w * DD;
    float s = 0.f;
    #pragma unroll
    for (int j = lane; j < DD; j += 32) { float v = row[j]; s = fmaf(v, v, s); }
    #pragma unroll
    for (int o = 16; o; o >>= 1) s += __shfl_xor_sync(0xffffffffu, s, o);
    if (lane == 0) g_c2[w] = s;
}
__global__ void finalize_k(const float* __restrict__ x, float* __restrict__ out) {
    size_t i = (size_t)blockIdx.x * blockDim.x + threadIdx.x;
    float4 xv = ((const float4*)x)[i];
    float4 rv = ((const float4*)g_res)[i];
    float4 o; o.x = xv.x - rv.x; o.y = xv.y - rv.y; o.z = xv.z - rv.z; o.w = xv.w - rv.w;
    ((float4*)out)[i] = o;
}

// ---------------- main stage kernel ----------------
__global__ void __launch_bounds__(NTHREADS, 2)
rvq_hmma_k(int s, const float* __restrict__ cb, float* __restrict__ outCodes, int writeCodes) {
    extern __shared__ char smraw[];
    uint32_t* Ab   = (uint32_t*)smraw;          // [2][4096]
    uint32_t* Bb   = Ab + 8192;                 // [2][4096]
    float*    Su   = (float*)(Bb + 8192);       // [128*32]
    float*    fin1 = Su + 4096;                 // [128][2]
    float*    fin2 = fin1 + 256;
    int*      finc = (int*)(fin2 + 256);
    int*      codes_sm = finc + 256;            // [128]
    int*      flags    = codes_sm + 128;        // [128]
    float*    redd = (float*)(flags + 128);     // [256]
    int*      redc = (int*)(redd + 256);        // [256]
    int*      nflag = redc + 256;

    const int t = threadIdx.x, lane = t & 31, w = t >> 5;
    const int mg = w >> 1, nh = w & 1;
    const int b = blockIdx.x;
    const long rowBase = (long)b * ROWS;

    const uint32_t* afr = g_afrag + (size_t)b * (8 * 4096);
    const uint32_t* bfr = g_bfrag + (size_t)s * (8 * 8 * 4096);
    const float*    c2p = g_c2 + s * KK;

    if (t == 0) *nflag = 0;

    const uint32_t AbA = (uint32_t)__cvta_generic_to_shared(Ab);
    const uint32_t BbA = (uint32_t)__cvta_generic_to_shared(Bb);

    // stage tile 0 (cc=0, dc=0) into buffer 0
    #pragma unroll
    for (int i = 0; i < 4; i++) {
        int u = t + i * NTHREADS;
        cpasync16(AbA + u * 16, &afr[(size_t)u * 4]);
        cpasync16(BbA + u * 16, &bfr[(size_t)u * 4]);
    }
    asm volatile("cp.async.commit_group;" ::: "memory");

    float acc[2][8][4];
    float L1[4], L2[4]; int C1[4];
    #pragma unroll
    for (int i = 0; i < 4; i++) { L1[i] = 3.4e38f; L2[i] = 3.4e38f; C1[i] = 0; }

    for (int jt = 0; jt < 64; jt++) {
        asm volatile("cp.async.wait_group 0;" ::: "memory");
        __syncthreads();
        const int cc = jt >> 3, dc = jt & 7, pb = jt & 1;

        if (jt < 63) {
            const int j = jt + 1, jcc = j >> 3, jdc = j & 7, qb = j & 1;
            #pragma unroll
            for (int i = 0; i < 4; i++) {
                int u = t + i * NTHREADS;
                cpasync16(AbA + qb * 16384 + u * 16, &afr[(size_t)jdc * 4096 + u * 4]);
                cpasync16(BbA + qb * 16384 + u * 16, &bfr[((size_t)jcc * 8 + jdc) * 4096 + u * 4]);
            }
            asm volatile("cp.async.commit_group;" ::: "memory");
        }

        const uint32_t* A = Ab + pb * 4096;
        const uint32_t* B = Bb + pb * 4096;

        if (dc == 0) {
            #pragma unroll
            for (int m = 0; m < 2; m++)
                #pragma unroll
                for (int n = 0; n < 8; n++)
                    #pragma unroll
                    for (int q = 0; q < 4; q++) acc[m][n][q] = 0.f;
        }

        #pragma unroll
        for (int ks = 0; ks < 4; ks++) {
            uint4 a0 = *(const uint4*)&A[(((mg * 2 + 0) * 4 + ks) * 32 + lane) * 4];
            uint4 a1 = *(const uint4*)&A[(((mg * 2 + 1) * 4 + ks) * 32 + lane) * 4];
            #pragma unroll
            for (int nt = 0; nt < 8; nt++) {
                uint2 bb = *(const uint2*)&B[(((nh * 8 + nt) * 4 + ks) * 32 + lane) * 2];
                MMA_TF32(acc[0][nt], a0, bb);
                MMA_TF32(acc[1][nt], a1, bb);
            }
        }

        if (dc == 7) {
            // dist = c2 - 2*dot; track per-lane top-2 per (mt, row-slot) combo
            #pragma unroll
            for (int mt = 0; mt < 2; mt++)
                #pragma unroll
                for (int nt = 0; nt < 8; nt++)
                    #pragma unroll
                    for (int jj = 0; jj < 4; jj++) {
                        int code = cc * 128 + nh * 64 + nt * 8 + 2 * (lane & 3) + (jj & 1);
                        float dist = fmaf(-2.f, acc[mt][nt][jj], __ldg(&c2p[code]));
                        int cbo = mt * 2 + (jj >> 1);
                        if (dist < L1[cbo] || (dist == L1[cbo] && code < C1[cbo])) {
                            L2[cbo] = L1[cbo]; L1[cbo] = dist; C1[cbo] = code;
                        } else if (dist < L2[cbo]) L2[cbo] = dist;
                    }
        }
    }

    // cross-lane merge (4 lanes share each row) and publish per-warp result
    #pragma unroll
    for (int cbo = 0; cbo < 4; cbo++) {
        float l1 = L1[cbo], l2 = L2[cbo]; int c1 = C1[cbo];
        #pragma unroll
        for (int o = 1; o <= 2; o <<= 1) {
            float o1 = __shfl_xor_sync(0xffffffffu, l1, o);
            float o2 = __shfl_xor_sync(0xffffffffu, l2, o);
            int   oc = __shfl_xor_sync(0xffffffffu, c1, o);
            float n2 = fminf(fmaxf(l1, o1), fminf(l2, o2));
            if (o1 < l1 || (o1 == l1 && oc < c1)) { l1 = o1; c1 = oc; }
            l2 = n2;
        }
        if ((lane & 3) == 0) {
            int mt = cbo >> 1, rs = cbo & 1;
            int row = mg * 32 + mt * 16 + rs * 8 + (lane >> 2);
            fin1[row * 2 + nh] = l1; fin2[row * 2 + nh] = l2; finc[row * 2 + nh] = c1;
        }
    }
    __syncthreads();

    // merge the two n-halves; margin test
    if (t < ROWS) {
        float x1 = fin1[t * 2], x2 = fin2[t * 2];  int xc = finc[t * 2];
        float y1 = fin1[t * 2 + 1], y2 = fin2[t * 2 + 1]; int yc = finc[t * 2 + 1];
        float f1, f2; int fc;
        if (y1 < x1 || (y1 == x1 && yc < xc)) { f1 = y1; fc = yc; f2 = fminf(x1, y2); }
        else                                  { f1 = x1; fc = xc; f2 = fminf(y1, x2); }
        codes_sm[t] = fc;
        if (f2 - f1 < MARGIN) { int i = atomicAdd(nflag, 1); flags[i] = t; }
    }
    __syncthreads();

    // exact fp32 recompute for near-tie rows
    const int nf = *nflag;
    for (int f = 0; f < nf; f++) {
        int rl = flags[f];
        const float* rrow = &g_res[(rowBase + rl) * DD];
        float bd = 3.4e38f; int bc = 0;
        for (int k = t; k < KK; k += NTHREADS) {
            const float* crow = &cb[((size_t)s * KK + k) * DD];
            float dot = 0.f;
            #pragma unroll 8
            for (int d = 0; d < DD; d++) dot = fmaf(rrow[d], crow[d], dot);
            float dist = fmaf(-2.f, dot, c2p[k]);
            if (dist < bd) { bd = dist; bc = k; }
        }
        redd[t] = bd; redc[t] = bc;
        __syncthreads();
        for (int off = NTHREADS / 2; off; off >>= 1) {
            if (t < off) {
                float od = redd[t + off]; int oc = redc[t + off];
                if (od < redd[t] || (od == redd[t] && oc < redc[t])) { redd[t] = od; redc[t] = oc; }
            }
            __syncthreads();
        }
        if (t == 0) codes_sm[rl] = redc[0];
        __syncthreads();
    }

    if (writeCodes && t < ROWS)
        outCodes[(rowBase + t) * NQ + s] = (float)codes_sm[t];

    // residual update (+ write next stage's A fragments)
    for (int dc = 0; dc < 8; dc++) {
        __syncthreads();
        {
            int r = t >> 1, ch = t & 1;
            int code = codes_sm[r];
            const float* crow = cb + ((size_t)s * KK + code) * DD + dc * 32 + ch * 16;
            float* rrow = g_res + (rowBase + r) * DD + dc * 32 + ch * 16;
            #pragma unroll
            for (int q = 0; q < 4; q++) {
                float4 rv = *(float4*)&rrow[q * 4];
                const float4 cv = *(const float4*)&crow[q * 4];
                rv.x -= cv.x; rv.y -= cv.y; rv.z -= cv.z; rv.w -= cv.w;
                *(float4*)&rrow[q * 4] = rv;
                *(float4*)&Su[r * 32 + ch * 16 + q * 4] = rv;
            }
        }
        __syncthreads();
        if (s < NQ - 1) {
            #pragma unroll
            for (int i = 0; i < 4; i++) {
                int p = t + i * NTHREADS;
                int pl = p & 31, ks = (p >> 5) & 3, mt = (p >> 7) & 1, pg = (p >> 8) & 3;
                int r0 = pg * 32 + mt * 16 + (pl >> 2), c0 = ks * 8 + (pl & 3);
                uint4 v;
                v.x = to_tf32(Su[r0 * 32 + c0]);
                v.y = to_tf32(Su[(r0 + 8) * 32 + c0]);
                v.z = to_tf32(Su[r0 * 32 + c0 + 4]);
                v.w = to_tf32(Su[(r0 + 8) * 32 + c0 + 4]);
                *(uint4*)&g_afrag[((size_t)b * 8 + dc) * 4096 + (size_t)p * 4] = v;
            }
        }
    }
}

// ---------------- launch ----------------
extern "C" void kernel_launch(void* const* d_in, const int* in_sizes, int n_in,
                              void* d_out, int out_size) {
    const float* x  = (const float*)d_in[0];
    const float* cb = (const float*)d_in[1];
    float* out = (float*)d_out;

    const long QE = (long)NTOT * DD;
    const long CE = (long)NTOT * NQ;

    int writeQ = (out_size >= QE) ? 1 : 0;
    float* outCodes = nullptr;
    int writeCodes = 0;
    if ((long)out_size >= QE + CE) { outCodes = out + QE; writeCodes = 1; }
    else if (!writeQ && (long)out_size >= CE) { outCodes = out; writeCodes = 1; }

    // smem: Ab/Bb 64KB + Su 16KB + fin 3KB + misc ~3.1KB
    const int SMEM = (8192 + 8192 + 4096 + 256 + 256) * 4 + 256 * 4 + 128 * 4 + 128 * 4
                   + 256 * 4 + 256 * 4 + 16;
    cudaFuncSetAttribute(rvq_hmma_k, cudaFuncAttributeMaxDynamicSharedMemorySize, SMEM);

    prep_b_k<<<(NQ * 8 * 8 * 16 * 4 * 32 + 255) / 256, 256>>>(cb);
    prep_a0_k<<<(1024 * 8 * 1024) / 256, 256>>>(x);
    copy_res_k<<<(NTOT * DD / 4) / 256, 256>>>(x);
    c2_k<<<(NQ * KK * 32 + 255) / 256, 256>>>(cb);

    for (int s = 0; s < NQ; s++)
        rvq_hmma_k<<<NTOT / ROWS, NTHREADS, SMEM>>>(s, cb, outCodes, writeCodes);

    if (writeQ)
        finalize_k<<<(NTOT * DD / 4) / 256, 256>>>(x, out);
}

// round 5
// speedup vs baseline: 2.3896x; 2.3896x over previous
#include <cuda_runtime.h>
#include <cstdint>

// Problem constants
#define DD   256
#define NQ   4
#define KK   1024
#define NTOT 131072

// Tiling
#define BM   128              // rows per CTA
#define BNC  128              // codes per chunk
#define BK   32               // d per staged chunk
#define NTHREADS 256
#define NITER 64              // 8 cc * 8 dk

// Scratch
__device__ float g_resT[(size_t)DD * NTOT];     // residual, transposed [d][n]
__device__ float g_cbT[(size_t)NQ * DD * KK];   // codebooks transposed [s][d][k]
__device__ float g_c2[NQ * KK];                 // ||c||^2 per code

// ---------------- packed f32x2 helpers ----------------
__device__ __forceinline__ unsigned long long pack2(float x) {
    unsigned long long r;
    unsigned int xi = __float_as_uint(x);
    asm("mov.b64 %0, {%1, %1};" : "=l"(r) : "r"(xi));
    return r;
}
__device__ __forceinline__ void ffma2(unsigned long long &acc,
                                      unsigned long long a,
                                      unsigned long long b) {
    asm("fma.rn.f32x2 %0, %1, %2, %0;" : "+l"(acc) : "l"(a), "l"(b));
}
__device__ __forceinline__ float2 unpack2(unsigned long long v) {
    unsigned int lo, hi;
    asm("mov.b64 {%0, %1}, %2;" : "=r"(lo), "=r"(hi) : "l"(v));
    return make_float2(__uint_as_float(lo), __uint_as_float(hi));
}
__device__ __forceinline__ void cpasync16(uint32_t s, const void* g) {
    asm volatile("cp.async.cg.shared.global [%0], [%1], 16;" :: "r"(s), "l"(g));
}
__device__ __forceinline__ void cpcommit() {
    asm volatile("cp.async.commit_group;" ::: "memory");
}

// ---------------- generic 32x32 tiled transpose: src[R][C] -> dst[C][R] ----------------
__global__ void transpose_k(const float* __restrict__ src, float* __restrict__ dst,
                            int R, int C, long srcBatch, long dstBatch) {
    __shared__ float tile[32][33];
    const float* s = src + (long)blockIdx.z * srcBatch;
    float*       d = dst + (long)blockIdx.z * dstBatch;
    int c0 = blockIdx.x * 32, r0 = blockIdx.y * 32;
    int tx = threadIdx.x, ty = threadIdx.y;           // 32 x 8
    #pragma unroll
    for (int i = 0; i < 32; i += 8)
        tile[ty + i][tx] = s[(long)(r0 + ty + i) * C + c0 + tx];
    __syncthreads();
    #pragma unroll
    for (int i = 0; i < 32; i += 8)
        d[(long)(c0 + ty + i) * R + r0 + tx] = tile[tx][ty + i];
}

// ---------------- ||c||^2 per code (one warp per code) ----------------
__global__ void c2_k(const float* __restrict__ cb) {
    int w = (blockIdx.x * blockDim.x + threadIdx.x) >> 5;
    int lane = threadIdx.x & 31;
    if (w >= NQ * KK) return;
    const float* row = cb + (long)w * DD;
    float s = 0.f;
    #pragma unroll
    for (int j = lane; j < DD; j += 32) { float v = row[j]; s = fmaf(v, v, s); }
    #pragma unroll
    for (int o = 16; o; o >>= 1) s += __shfl_xor_sync(0xffffffffu, s, o);
    if (lane == 0) g_c2[w] = s;
}

// ---------------- main per-stage kernel ----------------
// 256 threads: tx = t&15 (8 codes each), ty = t>>4 (8 rows each)
__global__ void __launch_bounds__(NTHREADS, 2)
rvq_stage_k(int s, float* __restrict__ outCodes, int writeCodes) {
    extern __shared__ float sm[];
    float* As = sm;                       // [3][32][128] residual chunks
    float* Bs = As + 3 * BK * BM;         // [3][32][128] codebook chunks
    int*   codes_sm = (int*)(Bs + 3 * BK * BNC);   // [128]

    const int t  = threadIdx.x;
    const int tx = t & 15, ty = t >> 4;
    const long rowBase = (long)blockIdx.x * BM;

    const float* cbT = g_cbT + (size_t)s * DD * KK;
    const float* c2p = g_c2 + s * KK;

    const uint32_t AsA = (uint32_t)__cvta_generic_to_shared(As);
    const uint32_t BsA = (uint32_t)__cvta_generic_to_shared(Bs);

    // stage chunk j into buffer j%3  (A: residual rows, B: codebook codes)
    #define STAGE(j) do {                                                         \
        const int _cc = (j) >> 3, _dk = (j) & 7;                                  \
        const uint32_t _ab = AsA + (uint32_t)((j) % 3) * (BK * BM * 4);           \
        const uint32_t _bb = BsA + (uint32_t)((j) % 3) * (BK * BNC * 4);          \
        _Pragma("unroll")                                                         \
        for (int k = 0; k < 4; k++) {                                             \
            int i4 = t + k * NTHREADS;                                            \
            int dd = i4 >> 5, q4 = i4 & 31;                                       \
            cpasync16(_ab + (uint32_t)(dd * BM + q4 * 4) * 4,                     \
                      &g_resT[(size_t)(_dk * BK + dd) * NTOT + rowBase + q4 * 4]);\
            cpasync16(_bb + (uint32_t)(dd * BNC + q4 * 4) * 4,                    \
                      &cbT[(size_t)(_dk * BK + dd) * KK + _cc * BNC + q4 * 4]);   \
        }                                                                         \
        cpcommit();                                                               \
    } while (0)

    STAGE(0);
    STAGE(1);

    float bestd[8];
    int   bestc[8];
    #pragma unroll
    for (int i = 0; i < 8; i++) { bestd[i] = 3.4e38f; bestc[i] = 0; }

    unsigned long long acc[8][4];   // [row rr][code-pair cp]

    for (int j = 0; j < NITER; j++) {
        if (j < NITER - 1) asm volatile("cp.async.wait_group 1;" ::: "memory");
        else               asm volatile("cp.async.wait_group 0;" ::: "memory");
        __syncthreads();

        // prefetch j+2 into buffer (j+2)%3 == (j-1)%3 — safe: all warps passed
        // the barrier above, so compute(j-1) is complete everywhere.
        if (j + 2 < NITER) STAGE(j + 2);

        const int cc = j >> 3, dk = j & 7;
        const float* abuf = As + (j % 3) * (BK * BM);
        const float* bbuf = Bs + (j % 3) * (BK * BNC);

        if (dk == 0) {
            #pragma unroll
            for (int rr = 0; rr < 8; rr++)
                #pragma unroll
                for (int cp = 0; cp < 4; cp++) acc[rr][cp] = 0ull;
        }

        #pragma unroll 8
        for (int dd = 0; dd < BK; dd++) {
            const float4 a0 = *(const float4*)&abuf[dd * BM + ty * 8];
            const float4 a1 = *(const float4*)&abuf[dd * BM + ty * 8 + 4];
            const ulonglong2 b0 = *(const ulonglong2*)&bbuf[dd * BNC + tx * 8];
            const ulonglong2 b1 = *(const ulonglong2*)&bbuf[dd * BNC + tx * 8 + 4];
            unsigned long long A[8];
            A[0] = pack2(a0.x); A[1] = pack2(a0.y); A[2] = pack2(a0.z); A[3] = pack2(a0.w);
            A[4] = pack2(a1.x); A[5] = pack2(a1.y); A[6] = pack2(a1.z); A[7] = pack2(a1.w);
            #pragma unroll
            for (int rr = 0; rr < 8; rr++) {
                ffma2(acc[rr][0], A[rr], b0.x);
                ffma2(acc[rr][1], A[rr], b0.y);
                ffma2(acc[rr][2], A[rr], b1.x);
                ffma2(acc[rr][3], A[rr], b1.y);
            }
        }

        if (dk == 7) {
            // dist = c2 - 2*dot ; lexicographic argmin (first-min on ties)
            #pragma unroll
            for (int rr = 0; rr < 8; rr++) {
                #pragma unroll
                for (int cp = 0; cp < 4; cp++) {
                    float2 dv = unpack2(acc[rr][cp]);
                    int cg0 = cc * BNC + tx * 8 + 2 * cp;
                    float d0 = fmaf(-2.f, dv.x, __ldg(&c2p[cg0]));
                    float d1 = fmaf(-2.f, dv.y, __ldg(&c2p[cg0 + 1]));
                    if (d0 < bestd[rr] || (d0 == bestd[rr] && cg0 < bestc[rr])) { bestd[rr] = d0; bestc[rr] = cg0; }
                    if (d1 < bestd[rr] || (d1 == bestd[rr] && cg0 + 1 < bestc[rr])) { bestd[rr] = d1; bestc[rr] = cg0 + 1; }
                }
            }
        }
    }
    #undef STAGE

    // cross-thread argmin: the 16 threads sharing ty are contiguous lanes (0-15 / 16-31)
    #pragma unroll
    for (int rr = 0; rr < 8; rr++) {
        float d = bestd[rr]; int c = bestc[rr];
        #pragma unroll
        for (int o = 8; o; o >>= 1) {
            float od = __shfl_xor_sync(0xffffffffu, d, o);
            int   oc = __shfl_xor_sync(0xffffffffu, c, o);
            if (od < d || (od == d && oc < c)) { d = od; c = oc; }
        }
        if (tx == 0) {
            int row = ty * 8 + rr;
            codes_sm[row] = c;
            if (writeCodes) outCodes[(rowBase + row) * NQ + s] = (float)c;
        }
    }
    __syncthreads();

    // residual update: g_resT[d][rowBase+r] -= cbT[d][code_r]
    for (int i = t; i < DD * BM; i += NTHREADS) {
        int d = i >> 7, r = i & 127;
        int code = codes_sm[r];
        size_t gi = (size_t)d * NTOT + rowBase + r;
        g_resT[gi] = g_resT[gi] - cbT[(size_t)d * KK + code];
    }
}

// ---------------- finalize: quantised[n][d] = x[n][d] - resT[d][n] ----------------
__global__ void finalize_k(const float* __restrict__ x, float* __restrict__ out) {
    __shared__ float tile[32][33];
    int n0 = blockIdx.x * 32, d0 = blockIdx.y * 32;
    int tx = threadIdx.x, ty = threadIdx.y;   // 32 x 8
    #pragma unroll
    for (int i = 0; i < 32; i += 8)
        tile[ty + i][tx] = g_resT[(size_t)(d0 + ty + i) * NTOT + n0 + tx];
    __syncthreads();
    #pragma unroll
    for (int i = 0; i < 32; i += 8) {
        long n = n0 + ty + i;
        int  d = d0 + tx;
        out[n * DD + d] = x[n * DD + d] - tile[tx][ty + i];
    }
}

// ---------------- launch ----------------
extern "C" void kernel_launch(void* const* d_in, const int* in_sizes, int n_in,
                              void* d_out, int out_size) {
    const float* x  = (const float*)d_in[0];
    const float* cb = (const float*)d_in[1];
    float* out = (float*)d_out;

    const long QE = (long)NTOT * DD;
    const long CE = (long)NTOT * NQ;

    int writeQ = (out_size >= QE) ? 1 : 0;
    float* outCodes = nullptr;
    int writeCodes = 0;
    if ((long)out_size >= QE + CE) { outCodes = out + QE; writeCodes = 1; }
    else if (!writeQ && (long)out_size >= CE) { outCodes = out; writeCodes = 1; }

    const int SMEM = (3 * BK * BM + 3 * BK * BNC) * 4 + BM * 4;   // 96.5 KB
    cudaFuncSetAttribute(rvq_stage_k, cudaFuncAttributeMaxDynamicSharedMemorySize, SMEM);

    float* cbT_ptr = nullptr;
    cudaGetSymbolAddress((void**)&cbT_ptr, g_cbT);
    float* resT_ptr = nullptr;
    cudaGetSymbolAddress((void**)&resT_ptr, g_resT);

    dim3 tb(32, 8);
    transpose_k<<<dim3(DD / 32, KK / 32, NQ), tb>>>(cb, cbT_ptr, KK, DD,
                                                    (long)KK * DD, (long)DD * KK);
    transpose_k<<<dim3(DD / 32, NTOT / 32, 1), tb>>>(x, resT_ptr, NTOT, DD, 0, 0);
    c2_k<<<(NQ * KK * 32 + 255) / 256, 256>>>(cb);

    for (int s = 0; s < NQ; s++)
        rvq_stage_k<<<NTOT / BM, NTHREADS, SMEM>>>(s, outCodes, writeCodes);

    if (writeQ)
        finalize_k<<<dim3(NTOT / 32, DD / 32), tb>>>(x, out);
}